// round 16
// baseline (speedup 1.0000x reference)
#include <cuda_runtime.h>
#include <cuda_fp16.h>
#include <math.h>
#include <stdint.h>

// MADE/IAF layer, fp16 mma.sync m16n8k16 + cp.async pipeline + ldmatrix.
//   zp = z[:, perm]
//   h  = relu(zp @ (W1*M1) + b1)          M=4096 K=1024 N=4096
//   r  = h @ (W2*M2) + b2                 M=4096 K=4096 N=2048
//   x  = zp*exp(log_s)+mu ; scatter by perm ; log_det = sum(log_s)
// Masks baked into transposed fp16 weights at prep time.
// All-zero masked B k-tiles skipped (exact-zero contributions).
// 512-thread CTAs (BM=256): 16 warps/SM -> 4 per SMSP for latency hiding.

#define BM 256
#define BN 128
#define BK 32
#define NTH 512
#define NSTG 4
#define A_BYTES 16384             // 256 rows x 64B
#define B_BYTES 8192              // 128 rows x 64B
#define STG_BYTES (A_BYTES + B_BYTES)
#define SMEM_TOTAL (NSTG * STG_BYTES)   // 96 KB

__device__ __half g_zph[4096L * 1024];   //  8.4 MB  zp fp16 [m][D]
__device__ __half g_ht [4096L * 4096];   // 33.6 MB  h  fp16 [m][H]
__device__ __half g_w1t[4096L * 1024];   //  8.4 MB  (W1*M1)^T fp16 [H][D]
__device__ __half g_w2t[2048L * 4096];   // 16.8 MB  (W2*M2)^T fp16 [2D][H]
__device__ float  g_res[4096L * 2048];   // 33.6 MB

__device__ __forceinline__ uint32_t smem_u32(const void* p) {
    uint32_t a;
    asm("{ .reg .u64 t; cvta.to.shared.u64 t, %1; cvt.u32.u64 %0, t; }" : "=r"(a) : "l"(p));
    return a;
}
__device__ __forceinline__ uint32_t h2pack(float lo, float hi) {
    uint32_t w;
    asm("cvt.rn.f16x2.f32 %0, %1, %2;" : "=r"(w) : "f"(hi), "f"(lo));
    return w;
}
__device__ __forceinline__ void mma16(float* d,
                                      uint32_t a0, uint32_t a1, uint32_t a2, uint32_t a3,
                                      uint32_t b0, uint32_t b1) {
    asm volatile(
        "mma.sync.aligned.m16n8k16.row.col.f32.f16.f16.f32 "
        "{%0,%1,%2,%3}, {%4,%5,%6,%7}, {%8,%9}, {%0,%1,%2,%3};"
        : "+f"(d[0]), "+f"(d[1]), "+f"(d[2]), "+f"(d[3])
        : "r"(a0), "r"(a1), "r"(a2), "r"(a3), "r"(b0), "r"(b1));
}
__device__ __forceinline__ void ldm4(uint32_t& r0, uint32_t& r1,
                                     uint32_t& r2, uint32_t& r3, uint32_t addr) {
    asm volatile("ldmatrix.sync.aligned.m8n8.x4.shared.b16 {%0,%1,%2,%3}, [%4];"
                 : "=r"(r0), "=r"(r1), "=r"(r2), "=r"(r3) : "r"(addr));
}
#define CPA16(dst, src) \
    asm volatile("cp.async.cg.shared.global [%0], [%1], 16;" :: "r"(dst), "l"(src))
#define CPA_COMMIT() asm volatile("cp.async.commit_group;" ::: "memory")
#define CPA_WAIT2()  asm volatile("cp.async.wait_group 2;" ::: "memory")

// ---- prep: masked transpose W[K][N] -> Wt[N][K] fp16 ----
template <int MODE>
__global__ void wt_kernel(const float* __restrict__ W, __half* __restrict__ Wt,
                          int K, int N, int D)
{
    __shared__ float tile[32][33];
    int k0 = blockIdx.x * 32, n0 = blockIdx.y * 32;
    int x = threadIdx.x, y = threadIdx.y;    // 32 x 8
#pragma unroll
    for (int r = 0; r < 32; r += 8)
        tile[y + r][x] = W[(size_t)(k0 + y + r) * N + n0 + x];
    __syncthreads();
    int Dm1 = D - 1;
#pragma unroll
    for (int r = 0; r < 32; r += 8) {
        int n = n0 + y + r, k = k0 + x;
        float v = tile[x][y + r];
        bool keep = (MODE == 1) ? ((n % Dm1) >= k) : ((n % D) > (k % Dm1));
        Wt[(size_t)n * K + k] = __float2half(keep ? v : 0.f);
    }
}

__global__ void zp_h_kernel(const float* __restrict__ z,
                            const int* __restrict__ perm,
                            int Brows, int D) {
    int idx = blockIdx.x * blockDim.x + threadIdx.x;
    if (idx < Brows * D) {
        int b = idx / D;
        int d = idx - b * D;
        g_zph[idx] = __float2half(z[(size_t)b * D + perm[d]]);
    }
}

// MODE 1: A=g_zph, B=g_w1t, bias+relu -> g_ht (fp16)
// MODE 2: A=g_ht,  B=g_w2t, bias      -> g_res (f32)
template <int MODE>
__global__ void __launch_bounds__(NTH)
gemm_cp(const float* __restrict__ bias, int N, int K, int D)
{
    const __half* __restrict__ A  = (MODE == 1) ? g_zph : g_ht;
    const __half* __restrict__ Bt = (MODE == 1) ? g_w1t : g_w2t;

    extern __shared__ char sm[];
    const uint32_t smu = smem_u32(sm);

    const int tid  = threadIdx.x;
    const int wid  = tid >> 5;
    const int lane = tid & 31;
    const int gq   = lane >> 2;
    const int tq   = lane & 3;
    const int row0 = blockIdx.x * BM;   // M fast
    const int col0 = blockIdx.y * BN;
    const int Dm1  = D - 1;

    const int mwarp = (wid & 3) * 64;   // 4 warp-rows of 64
    const int nwarp = (wid >> 2) * 32;  // 4 warp-cols of 32

    // ---- tile-skip bounds ----
    int maxkey;
    if (MODE == 1) {
        int m0 = col0 % Dm1;
        maxkey = (m0 + BN - 1 >= Dm1) ? (Dm1 - 1) : (m0 + BN - 1);
    } else {
        maxkey = (col0 % D) + BN - 1;
    }
    const int nT = K / BK;
    const int nT1 = (MODE == 1) ? min(nT, maxkey / BK + 1) : nT;

    // ---- cp.async maps: 2 A-chunks + 1 B-chunk (16B) per thread per stage ----
    uint32_t adst[2], bdst;
    const __half* asrc[2];
    const __half* bsrc;
#pragma unroll
    for (int i = 0; i < 2; i++) {
        int slot = tid + i * NTH;        // 0..1023
        int r  = slot >> 2;              // row 0..255
        int cc = slot & 3;               // 16B chunk
        uint32_t off = (uint32_t)((r << 6) + ((cc ^ ((r >> 1) & 3)) << 4));
        adst[i] = smu + off;
        asrc[i] = A + (size_t)(row0 + r) * K + cc * 8;
    }
    {
        int r  = tid >> 2;               // row 0..127
        int cc = tid & 3;
        uint32_t off = (uint32_t)((r << 6) + ((cc ^ ((r >> 1) & 3)) << 4));
        bdst = smu + A_BYTES + off;
        bsrc = Bt + (size_t)(col0 + r) * K + cc * 8;
    }

    // ---- ldmatrix lane address components ----
    const int mat = lane >> 3;
    const int arow_off = ((mat & 1) << 3) + (lane & 7);
    const int ackbit   = mat >> 1;
    const int brow_off = ((mat >> 1) << 3) + (lane & 7);
    const int bckbit   = mat & 1;

    uint32_t abase[4]; int aswz[4];
#pragma unroll
    for (int mt = 0; mt < 4; mt++) {
        int r = mwarp + mt * 16 + arow_off;
        abase[mt] = (uint32_t)(r << 6);
        aswz[mt]  = (r >> 1) & 3;
    }
    uint32_t bbase[2]; int bswz[2];
#pragma unroll
    for (int np = 0; np < 2; np++) {
        int r = nwarp + np * 16 + brow_off;
        bbase[np] = (uint32_t)(r << 6);
        bswz[np]  = (r >> 1) & 3;
    }

    float acc[4][4][4];
#pragma unroll
    for (int mt = 0; mt < 4; mt++)
#pragma unroll
        for (int nt = 0; nt < 4; nt++)
#pragma unroll
            for (int e = 0; e < 4; e++) acc[mt][nt][e] = 0.f;

    auto nxt = [&](int t) -> int {
        int tn = t + 1;
        if (MODE == 1) return (tn >= nT1) ? nT : tn;
        while (tn < nT) {
            int r = (tn * BK) % Dm1;
            int minh = (r + BK - 1 > Dm1 - 1) ? 0 : r;   // wrap hits 0
            if (minh < maxkey) break;
            tn++;
        }
        return tn;
    };

#define ISSUE(T, S)                                                   \
    {                                                                  \
        if ((T) < nT) {                                                \
            uint32_t base_ = (uint32_t)((S) * STG_BYTES);              \
            const int ko_ = (T) * BK;                                  \
            CPA16(adst[0] + base_, asrc[0] + ko_);                     \
            CPA16(adst[1] + base_, asrc[1] + ko_);                     \
            CPA16(bdst + base_, bsrc + ko_);                           \
        }                                                              \
        CPA_COMMIT();                                                  \
    }

    int t0 = 0;
    int t1 = nxt(t0);
    int t2 = (t1 < nT) ? nxt(t1) : nT;
    ISSUE(t0, 0);
    ISSUE(t1, 1);
    ISSUE(t2, 2);
    int tIss = t2;

    int tc = 0, p = 0;
    while (tc < nT) {
        CPA_WAIT2();                 // stage p landed
        __syncthreads();             // readers of slot (p-1)&3 retired
        tIss = (tIss < nT) ? nxt(tIss) : nT;
        ISSUE(tIss, (p + 3) & 3);

        const uint32_t ab = smu + (uint32_t)((p & 3) * STG_BYTES);
        const uint32_t bb = ab + A_BYTES;

        uint32_t af[2][4][4], bf[2][4][2];
#pragma unroll
        for (int ks = 0; ks < 2; ks++) {
            const int ack = (ks * 2 + ackbit);
            const int bck = (ks * 2 + bckbit);
#pragma unroll
            for (int mt = 0; mt < 4; mt++)
                ldm4(af[ks][mt][0], af[ks][mt][1], af[ks][mt][2], af[ks][mt][3],
                     ab + abase[mt] + (uint32_t)(((ack ^ aswz[mt]) & 3) << 4));
#pragma unroll
            for (int np = 0; np < 2; np++)
                ldm4(bf[ks][2 * np][0], bf[ks][2 * np][1],
                     bf[ks][2 * np + 1][0], bf[ks][2 * np + 1][1],
                     bb + bbase[np] + (uint32_t)(((bck ^ bswz[np]) & 3) << 4));
        }
#pragma unroll
        for (int ks = 0; ks < 2; ks++)
#pragma unroll
            for (int mt = 0; mt < 4; mt++)
#pragma unroll
                for (int nt = 0; nt < 4; nt++)
                    mma16(acc[mt][nt],
                          af[ks][mt][0], af[ks][mt][1], af[ks][mt][2], af[ks][mt][3],
                          bf[ks][nt][0], bf[ks][nt][1]);

        tc = nxt(tc);
        p++;
    }
#undef ISSUE

    // ---- epilogue ----
#pragma unroll
    for (int mt = 0; mt < 4; mt++) {
        int r0 = row0 + mwarp + mt * 16 + gq;
#pragma unroll
        for (int nt = 0; nt < 4; nt++) {
            int c = col0 + nwarp + nt * 8 + 2 * tq;
            float bx = bias[c], by = bias[c + 1];
            float v00 = acc[mt][nt][0] + bx, v01 = acc[mt][nt][1] + by;
            float v10 = acc[mt][nt][2] + bx, v11 = acc[mt][nt][3] + by;
            if (MODE == 1) {
                v00 = fmaxf(v00, 0.f); v01 = fmaxf(v01, 0.f);
                v10 = fmaxf(v10, 0.f); v11 = fmaxf(v11, 0.f);
                *(uint32_t*)(&g_ht[(size_t)r0 * N + c])       = h2pack(v00, v01);
                *(uint32_t*)(&g_ht[(size_t)(r0 + 8) * N + c]) = h2pack(v10, v11);
            } else {
                float2 a0; a0.x = v00; a0.y = v01;
                float2 a1; a1.x = v10; a1.y = v11;
                *(float2*)(&g_res[(size_t)r0 * N + c])       = a0;
                *(float2*)(&g_res[(size_t)(r0 + 8) * N + c]) = a1;
            }
        }
    }
}

__global__ void finish_kernel(const float* __restrict__ z,
                              const int* __restrict__ perm,
                              float* __restrict__ out,
                              int Brows, int D, int out_size)
{
    int b = blockIdx.x;
    int tid = threadIdx.x;
    const float* mu = g_res + (size_t)b * 2 * D;
    const float* ls = mu + D;
    const float* zrow = z + (size_t)b * D;

    float partial = 0.f;
    for (int d = tid; d < D; d += blockDim.x) {
        float l = ls[d];
        float x = zrow[perm[d]] * expf(l) + mu[d];
        out[(size_t)b * D + perm[d]] = x;
        partial += l;
    }

    __shared__ float red[256];
    red[tid] = partial;
    __syncthreads();
    for (int s = 128; s > 0; s >>= 1) {
        if (tid < s) red[tid] += red[tid + s];
        __syncthreads();
    }
    if (tid == 0 && out_size >= Brows * D + Brows)
        out[(size_t)Brows * D + b] = red[0];
}

extern "C" void kernel_launch(void* const* d_in, const int* in_sizes, int n_in,
                              void* d_out, int out_size)
{
    const float* z   = (const float*)d_in[0];
    const float* W1  = (const float*)d_in[1];
    const float* b1  = (const float*)d_in[2];
    const float* W2  = (const float*)d_in[3];
    const float* b2  = (const float*)d_in[4];
    const int*  perm = (const int*)d_in[5];

    const int D     = in_sizes[5];          // 1024
    const int H     = in_sizes[2];          // 4096
    const int Brows = in_sizes[0] / D;      // 4096
    const int N2    = in_sizes[4];          // 2048

    float* out = (float*)d_out;

    static bool attr_set = false;
    if (!attr_set) {
        cudaFuncSetAttribute(gemm_cp<1>, cudaFuncAttributeMaxDynamicSharedMemorySize, SMEM_TOTAL);
        cudaFuncSetAttribute(gemm_cp<2>, cudaFuncAttributeMaxDynamicSharedMemorySize, SMEM_TOTAL);
        attr_set = true;
    }

    {
        __half* w1t; cudaGetSymbolAddress((void**)&w1t, g_w1t);
        __half* w2t; cudaGetSymbolAddress((void**)&w2t, g_w2t);
        dim3 blk(32, 8);
        dim3 gw1(D / 32, H / 32);
        wt_kernel<1><<<gw1, blk>>>(W1, w1t, D, H, D);
        dim3 gw2(H / 32, N2 / 32);
        wt_kernel<2><<<gw2, blk>>>(W2, w2t, H, N2, D);
    }
    zp_h_kernel<<<(Brows * D + 255) / 256, 256>>>(z, perm, Brows, D);

    dim3 g1(Brows / BM, H / BN);
    gemm_cp<1><<<g1, NTH, SMEM_TOTAL>>>(b1, H, D, D);

    dim3 g2(Brows / BM, N2 / BN);
    gemm_cp<2><<<g2, NTH, SMEM_TOTAL>>>(b2, N2, H, D);

    finish_kernel<<<Brows, 256>>>(z, perm, out, Brows, D, out_size);
}